// round 1
// baseline (speedup 1.0000x reference)
#include <cuda_runtime.h>
#include <cuda_bf16.h>

// ---------------------------------------------------------------------------
// GCNLayer_V2: trimmed-mean neighbor aggregation + linear + bias + relu
//
// Inputs (metadata order):
//   d_in[0] h      float [20000,128]
//   d_in[1] norm   float [20000,1]
//   d_in[2] weight float [128,128]
//   d_in[3] bias   float [128]
//   d_in[4] nbr    int32 [20000,32]
//   d_in[5] deg    int32 [20000]
// Output: float [20000,128] = relu(accum @ W + b)
// ---------------------------------------------------------------------------

#define NNODE 20000
#define FDIM 128
#define DMAX 32

// scratch for the aggregated features (device global: no allocation allowed)
__device__ float g_accum[NNODE * FDIM];

// ---------------------------------------------------------------------------
// Kernel 1: per-node, per-feature trimmed aggregation.
// Block = 128 threads (one per feature), grid = N nodes.
// Each thread does an in-register bitonic sort of (key=munged h, val=h*norm)
// pairs over the node's neighbors and sums ranks [b, n-b).
// ---------------------------------------------------------------------------

template <int S>
__device__ __forceinline__ float trimmed_sum(const float* __restrict__ h,
                                             const int* s_nbr,
                                             const float* s_norm,
                                             int n, int lo, int hi, int tid) {
    unsigned key[S];
    float val[S];

    // Gather keys (coalesced 512B row reads across the block) + payloads.
#pragma unroll
    for (int d = 0; d < S; ++d) {
        if (d < n) {
            int src = s_nbr[d];
            float x = __ldg(&h[src * FDIM + tid]);
            unsigned m = __float_as_uint(x);
            // order-preserving float->uint munge
            m = (m & 0x80000000u) ? ~m : (m | 0x80000000u);
            key[d] = m;
            val[d] = x * s_norm[d];
        } else {
            key[d] = 0xFFFFFFFFu;   // +inf sentinel: sorts past all valid
            val[d] = 0.0f;
        }
    }

    // Bitonic sort network, fully unrolled, keys ascending.
#pragma unroll
    for (int k = 2; k <= S; k <<= 1) {
#pragma unroll
        for (int j = k >> 1; j > 0; j >>= 1) {
#pragma unroll
            for (int i = 0; i < S; ++i) {
                int l = i ^ j;
                if (l > i) {
                    bool up = ((i & k) == 0);
                    bool p = up ? (key[i] > key[l]) : (key[i] < key[l]);
                    unsigned ka = key[i], kb = key[l];
                    float va = val[i], vb = val[l];
                    key[i] = p ? kb : ka;
                    key[l] = p ? ka : kb;
                    val[i] = p ? vb : va;
                    val[l] = p ? va : vb;
                }
            }
        }
    }

    // Sum payloads at ranks [lo, hi) in ascending rank order (matches jnp.sum).
    float ts = 0.0f;
#pragma unroll
    for (int r = 0; r < S; ++r) {
        bool sel = (r >= lo) && (r < hi);
        ts += sel ? val[r] : 0.0f;
    }
    return ts;
}

__global__ __launch_bounds__(FDIM, 4)
void agg_kernel(const float* __restrict__ h,
                const float* __restrict__ norm,
                const int* __restrict__ nbr,
                const int* __restrict__ deg,
                int nnode) {
    int node = blockIdx.x;
    if (node >= nnode) return;
    int tid = threadIdx.x;

    __shared__ int s_nbr[DMAX];
    __shared__ float s_norm[DMAX];
    __shared__ int s_n;
    __shared__ float s_nd;

    if (tid < DMAX) {
        int src = nbr[node * DMAX + tid];
        s_nbr[tid] = src;
        s_norm[tid] = norm[src];
    }
    if (tid == 0) {
        s_n = deg[node];
        s_nd = norm[node];
    }
    __syncthreads();

    int n = s_n;                 // block-uniform
    float normd = s_nd;
    float self0 = h[node * FDIM + tid] * normd;

    float acc;
    if (n <= 3) {
        // small-degree branch: n * self0 * norm
        acc = ((float)n * self0) * normd;
    } else {
        int braw = (n >> 1) - (1 - (n & 1));
        // match jnp: floor(float32(n) * float32(0.45))
        int bcap = (int)floorf(__fmul_rn((float)n, 0.45f));
        int b = min(braw, bcap);
        b = max(b, 1);
        int lo = b, hi = n - b;

        float ts;
        if (n <= 8)       ts = trimmed_sum<8>(h, s_nbr, s_norm, n, lo, hi, tid);
        else if (n <= 16) ts = trimmed_sum<16>(h, s_nbr, s_norm, n, lo, hi, tid);
        else              ts = trimmed_sum<32>(h, s_nbr, s_norm, n, lo, hi, tid);

        acc = (ts + self0 * (float)(2 * b)) * normd;
    }
    g_accum[node * FDIM + tid] = acc;
}

// ---------------------------------------------------------------------------
// Kernel 2: out = relu(accum @ W + bias)
// Block = 256 threads, tile = 32 rows x 128 cols; each thread owns 16 outputs
// (one column, 16 rows). W is transposed into padded shared memory so each
// thread streams its W column as conflict-free float4 LDS.
// ---------------------------------------------------------------------------

#define GEMM_TM 32
#define WT_PITCH 132   // 128 + 4 pad floats per transposed row
#define GEMM_SMEM_BYTES ((FDIM * WT_PITCH + GEMM_TM * FDIM) * 4)

__global__ __launch_bounds__(256)
void gemm_kernel(const float* __restrict__ W,
                 const float* __restrict__ bias,
                 float* __restrict__ out,
                 int nnode) {
    extern __shared__ float sm[];
    float* Wt = sm;                       // [128][132] : Wt[g*132 + f] = W[f][g]
    float* As = sm + FDIM * WT_PITCH;     // [32][128]

    int tid = threadIdx.x;

    // load + transpose W into shared (conflict-free writes: stride 132)
    for (int i = tid; i < FDIM * FDIM; i += 256) {
        int f = i >> 7;
        int g = i & 127;
        Wt[g * WT_PITCH + f] = W[i];
    }

    int row0 = blockIdx.x * GEMM_TM;
    // load accum tile (coalesced)
    for (int i = tid; i < GEMM_TM * FDIM; i += 256) {
        As[i] = g_accum[row0 * FDIM + i];
    }
    __syncthreads();

    int g = tid & 127;        // output column
    int rg = tid >> 7;        // 0/1 : which half of the 32 rows

    float o[16];
#pragma unroll
    for (int j = 0; j < 16; ++j) o[j] = 0.0f;

    const float4* wrow = reinterpret_cast<const float4*>(Wt + g * WT_PITCH);

#pragma unroll
    for (int f4 = 0; f4 < FDIM / 4; ++f4) {
        float4 w = wrow[f4];
#pragma unroll
        for (int j = 0; j < 16; ++j) {
            const float4 a = *reinterpret_cast<const float4*>(
                As + (rg * 16 + j) * FDIM + f4 * 4);
            o[j] = fmaf(w.x, a.x, o[j]);
            o[j] = fmaf(w.y, a.y, o[j]);
            o[j] = fmaf(w.z, a.z, o[j]);
            o[j] = fmaf(w.w, a.w, o[j]);
        }
    }

    float bg = __ldg(&bias[g]);
#pragma unroll
    for (int j = 0; j < 16; ++j) {
        int row = row0 + rg * 16 + j;
        if (row < nnode) {
            out[row * FDIM + g] = fmaxf(o[j] + bg, 0.0f);
        }
    }
}

// ---------------------------------------------------------------------------
// launch
// ---------------------------------------------------------------------------

extern "C" void kernel_launch(void* const* d_in, const int* in_sizes, int n_in,
                              void* d_out, int out_size) {
    const float* h    = (const float*)d_in[0];
    const float* norm = (const float*)d_in[1];
    const float* W    = (const float*)d_in[2];
    const float* bias = (const float*)d_in[3];
    const int*   nbr  = (const int*)d_in[4];
    const int*   deg  = (const int*)d_in[5];
    float* out = (float*)d_out;

    int nnode = in_sizes[5];   // 20000

    // opt into >48KB dynamic shared memory for the GEMM (idempotent)
    cudaFuncSetAttribute(gemm_kernel,
                         cudaFuncAttributeMaxDynamicSharedMemorySize,
                         GEMM_SMEM_BYTES);

    agg_kernel<<<nnode, FDIM>>>(h, norm, nbr, deg, nnode);

    int gemm_blocks = (nnode + GEMM_TM - 1) / GEMM_TM;   // 625
    gemm_kernel<<<gemm_blocks, 256, GEMM_SMEM_BYTES>>>(W, bias, out, nnode);
}

// round 2
// speedup vs baseline: 1.2807x; 1.2807x over previous
#include <cuda_runtime.h>
#include <cuda_bf16.h>
#include <math_constants.h>

// ---------------------------------------------------------------------------
// GCNLayer_V2: trimmed-mean neighbor aggregation + linear + bias + relu
//
// Inputs (metadata order):
//   d_in[0] h      float [20000,128]
//   d_in[1] norm   float [20000,1]
//   d_in[2] weight float [128,128]
//   d_in[3] bias   float [128]
//   d_in[4] nbr    int32 [20000,32]
//   d_in[5] deg    int32 [20000]
// Output: float [20000,128] = relu(accum @ W + b)
// ---------------------------------------------------------------------------

#define NNODE 20000
#define FDIM 128
#define DMAX 32

typedef unsigned long long ull;

// scratch for the aggregated features (device global: no allocation allowed)
__device__ float g_accum[NNODE * FDIM];

// ---------------------------------------------------------------------------
// Batcher odd-even merge sort network, generated at compile time.
// CE counts: S=8 -> 19, S=16 -> 63, S=32 -> 191 (vs bitonic 24/80/240).
// ---------------------------------------------------------------------------

template <int S>
struct OEMSNet {
    int a[200];
    int b[200];
    int count;

    constexpr void cmp(int i, int j) { a[count] = i; b[count] = j; ++count; }

    constexpr void merge(int lo, int n, int r) {
        int m = r * 2;
        if (m < n) {
            merge(lo, n, m);
            merge(lo + r, n, m);
            for (int i = lo + r; i + r < lo + n; i += m) cmp(i, i + r);
        } else {
            cmp(lo, lo + r);
        }
    }

    constexpr void sort(int lo, int n) {
        if (n > 1) {
            int m = n / 2;
            sort(lo, m);
            sort(lo + m, m);
            merge(lo, n, 1);
        }
    }

    constexpr OEMSNet() : a(), b(), count(0) { sort(0, S); }
};

// ---------------------------------------------------------------------------
// Kernel 1: per-node, per-feature trimmed aggregation.
// Block = 128 threads (one per feature), grid = N nodes.
// Each thread sorts (key = h value, val = h*norm) pairs over the node's
// neighbors with an in-register OEMS network and sums ranks [b, n-b).
// Float keys: ties only occur for duplicate src indices, whose payloads are
// identical, so tie order never affects the sum.
// ---------------------------------------------------------------------------

template <int S>
__device__ __forceinline__ float trimmed_sum(const float* __restrict__ h,
                                             const int* s_nbr,
                                             const float* s_norm,
                                             int n, int lo, int hi, int tid) {
    float key[S];
    float val[S];

    // Gather keys (coalesced 512B row reads across the block) + payloads.
#pragma unroll
    for (int d = 0; d < S; ++d) {
        if (d < n) {
            int src = s_nbr[d];
            float x = __ldg(&h[src * FDIM + tid]);
            key[d] = x;
            val[d] = x * s_norm[d];
        } else {
            key[d] = CUDART_INF_F;   // sentinel: sorts past all valid
            val[d] = 0.0f;
        }
    }

    // Odd-even merge sort, ascending keys.
    constexpr OEMSNet<S> net{};
#pragma unroll
    for (int p = 0; p < net.count; ++p) {
        const int i = net.a[p];
        const int l = net.b[p];
        float ki = key[i], kl = key[l];
        bool sw = ki > kl;
        key[i] = sw ? kl : ki;
        key[l] = sw ? ki : kl;
        float vi = val[i], vl = val[l];
        val[i] = sw ? vl : vi;
        val[l] = sw ? vi : vl;
    }

    // Sum payloads at ranks [lo, hi) in ascending rank order.
    float ts = 0.0f;
#pragma unroll
    for (int r = 0; r < S; ++r) {
        bool sel = (r >= lo) && (r < hi);
        ts += sel ? val[r] : 0.0f;
    }
    return ts;
}

__global__ __launch_bounds__(FDIM)
void agg_kernel(const float* __restrict__ h,
                const float* __restrict__ norm,
                const int* __restrict__ nbr,
                const int* __restrict__ deg,
                int nnode) {
    int node = blockIdx.x;
    if (node >= nnode) return;
    int tid = threadIdx.x;

    __shared__ int s_nbr[DMAX];
    __shared__ float s_norm[DMAX];
    __shared__ int s_n;
    __shared__ float s_nd;

    if (tid < DMAX) {
        int src = nbr[node * DMAX + tid];
        s_nbr[tid] = src;
        s_norm[tid] = norm[src];
    }
    if (tid == 0) {
        s_n = deg[node];
        s_nd = norm[node];
    }
    __syncthreads();

    int n = s_n;                 // block-uniform
    float normd = s_nd;
    float self0 = h[node * FDIM + tid] * normd;

    float acc;
    if (n <= 3) {
        acc = ((float)n * self0) * normd;
    } else {
        int braw = (n >> 1) - (1 - (n & 1));
        // match jnp: floor(float32(n) * float32(0.45))
        int bcap = (int)floorf(__fmul_rn((float)n, 0.45f));
        int b = min(braw, bcap);
        b = max(b, 1);
        int lo = b, hi = n - b;

        float ts;
        if (n <= 8)       ts = trimmed_sum<8>(h, s_nbr, s_norm, n, lo, hi, tid);
        else if (n <= 16) ts = trimmed_sum<16>(h, s_nbr, s_norm, n, lo, hi, tid);
        else              ts = trimmed_sum<32>(h, s_nbr, s_norm, n, lo, hi, tid);

        acc = (ts + self0 * (float)(2 * b)) * normd;
    }
    g_accum[node * FDIM + tid] = acc;
}

// ---------------------------------------------------------------------------
// Kernel 2: out = relu(accum @ W + bias)
// Block = 128 threads, tile = 64 rows x 128 cols; each thread owns an 8x8
// register tile (rows ty*8.., cols tx*8..). Accumulators are f32x2 packed
// over column pairs; inner product via fma.rn.f32x2 (FFMA2, PTX-only) which
// doubles fp32 FMA throughput. W stays in smem untransposed: column pairs
// are natural u64 loads; A-tile reads are warp-broadcast scalars.
// ---------------------------------------------------------------------------

#define GT_ROWS 64
#define GEMM_SMEM_BYTES ((FDIM * FDIM + GT_ROWS * FDIM) * 4)   // 96 KB

__device__ __forceinline__ void fma2(ull& d, ull a, ull b) {
    asm("fma.rn.f32x2 %0, %1, %2, %0;" : "+l"(d) : "l"(a), "l"(b));
}
__device__ __forceinline__ ull dup2(float x) {
    ull r;
    asm("mov.b64 %0, {%1, %1};" : "=l"(r) : "f"(x));
    return r;
}
__device__ __forceinline__ void unpack2(float& lo, float& hi, ull v) {
    asm("mov.b64 {%0, %1}, %2;" : "=f"(lo), "=f"(hi) : "l"(v));
}

__global__ __launch_bounds__(128, 2)
void gemm_kernel(const float* __restrict__ W,
                 const float* __restrict__ bias,
                 float* __restrict__ out,
                 int nnode) {
    extern __shared__ float sm[];
    float* Ws = sm;                    // [128][128] f32, same layout as W
    float* As = sm + FDIM * FDIM;      // [64 rows][128 f], row-major

    int tid = threadIdx.x;
    int row0 = blockIdx.x * GT_ROWS;

    // stage W (direct copy, coalesced float4)
    {
        const float4* Wg = reinterpret_cast<const float4*>(W);
        float4* Wsm = reinterpret_cast<float4*>(Ws);
        for (int i = tid; i < FDIM * FDIM / 4; i += 128) Wsm[i] = Wg[i];
    }
    // stage A tile (coalesced float4, zero-fill OOB rows)
    {
        float4* Asm = reinterpret_cast<float4*>(As);
        for (int i = tid; i < GT_ROWS * FDIM / 4; i += 128) {
            int r = i >> 5;                 // 32 float4 per row
            int row = row0 + r;
            float4 v = make_float4(0.f, 0.f, 0.f, 0.f);
            if (row < nnode)
                v = reinterpret_cast<const float4*>(g_accum)[row * 32 + (i & 31)];
            Asm[i] = v;
        }
    }
    __syncthreads();

    int tx = tid & 15;       // column group: cols tx*8 .. tx*8+7
    int ty = tid >> 4;       // row group:    rows ty*8 .. ty*8+7

    ull acc[32];             // acc[r*4+c2] covers (row ty*8+r, cols tx*8+2c2..+1)
#pragma unroll
    for (int i = 0; i < 32; ++i) acc[i] = 0ull;

    const ull* wbase = reinterpret_cast<const ull*>(Ws + tx * 8);
    const float* abase = As + ty * 8 * FDIM;

#pragma unroll 4
    for (int f = 0; f < FDIM; ++f) {
        ull w[4];
        const ull* wp = wbase + f * (FDIM / 2);
#pragma unroll
        for (int c2 = 0; c2 < 4; ++c2) w[c2] = wp[c2];

        float a_s[8];
#pragma unroll
        for (int r = 0; r < 8; ++r) a_s[r] = abase[r * FDIM + f];

#pragma unroll
        for (int r = 0; r < 8; ++r) {
            ull aa = dup2(a_s[r]);
#pragma unroll
            for (int c2 = 0; c2 < 4; ++c2) fma2(acc[r * 4 + c2], aa, w[c2]);
        }
    }

    // epilogue: bias + relu + store
    float bcol[8];
#pragma unroll
    for (int c = 0; c < 8; ++c) bcol[c] = __ldg(&bias[tx * 8 + c]);

#pragma unroll
    for (int r = 0; r < 8; ++r) {
        int row = row0 + ty * 8 + r;
        if (row < nnode) {
            float* orow = out + row * FDIM + tx * 8;
#pragma unroll
            for (int c2 = 0; c2 < 4; ++c2) {
                float lo, hi;
                unpack2(lo, hi, acc[r * 4 + c2]);
                float2 o;
                o.x = fmaxf(lo + bcol[2 * c2], 0.0f);
                o.y = fmaxf(hi + bcol[2 * c2 + 1], 0.0f);
                *reinterpret_cast<float2*>(orow + 2 * c2) = o;
            }
        }
    }
}

// ---------------------------------------------------------------------------
// launch
// ---------------------------------------------------------------------------

extern "C" void kernel_launch(void* const* d_in, const int* in_sizes, int n_in,
                              void* d_out, int out_size) {
    const float* h    = (const float*)d_in[0];
    const float* norm = (const float*)d_in[1];
    const float* W    = (const float*)d_in[2];
    const float* bias = (const float*)d_in[3];
    const int*   nbr  = (const int*)d_in[4];
    const int*   deg  = (const int*)d_in[5];
    float* out = (float*)d_out;

    int nnode = in_sizes[5];   // 20000

    cudaFuncSetAttribute(gemm_kernel,
                         cudaFuncAttributeMaxDynamicSharedMemorySize,
                         GEMM_SMEM_BYTES);

    agg_kernel<<<nnode, FDIM>>>(h, norm, nbr, deg, nnode);

    int gemm_blocks = (nnode + GT_ROWS - 1) / GT_ROWS;   // 313
    gemm_kernel<<<gemm_blocks, 128, GEMM_SMEM_BYTES>>>(W, bias, out, nnode);
}